// round 15
// baseline (speedup 1.0000x reference)
#include <cuda_runtime.h>
#include <cstdint>
#include <math.h>

#define NSAMP 128
#define NDIM  24
#define SPAIRS 8128        // C(128,2)
#define NPAIR2 4064        // SPAIRS / 2
#define FPAIRS 276         // C(24,2)
#define FS 2243328         // FPAIRS * SPAIRS
#define RCOND 2.3841858e-6f   // jax pinv: 10*max(M,N)*eps(f32)
#define SEPS 5.9604645e-8f    // slamch('E')
#define MAXTRIP 8
#define NCHUNK 45

// chunk tables: p, first q, trip count (q-range split into chunks of <=8)
__constant__ unsigned char c_p[NCHUNK] = {
    0,0,0, 1,1,1, 2,2,2, 3,3,3, 4,4,4, 5,5,5, 6,6,6,
    7,7, 8,8, 9,9, 10,10, 11,11, 12,12, 13,13, 14,14,
    15, 16, 17, 18, 19, 20, 21, 22 };
__constant__ unsigned char c_q0[NCHUNK] = {
    1,9,17, 2,10,18, 3,11,19, 4,12,20, 5,13,21, 6,14,22, 7,15,23,
    8,16, 9,17, 10,18, 11,19, 12,20, 13,21, 14,22, 15,23,
    16, 17, 18, 19, 20, 21, 22, 23 };
__constant__ unsigned char c_n[NCHUNK] = {
    8,8,7, 8,8,6, 8,8,5, 8,8,4, 8,8,3, 8,8,2, 8,8,1,
    8,8, 8,7, 8,6, 8,5, 8,4, 8,3, 8,2, 8,1,
    8, 7, 6, 5, 4, 3, 2, 1 };

__device__ __forceinline__ int row_start(int i, int n) {
    return (i * (2 * n - 1 - i)) >> 1;
}
__device__ __forceinline__ float fdivf(float a, float b) { return __fdividef(a, b); }
__device__ __forceinline__ float fsqrtf_a(float x) {
    float r; asm("sqrt.approx.f32 %0, %1;" : "=f"(r) : "f"(x)); return r;
}

// ---------------- LAPACK SLASV2 (rare slow path; netlib semantics) ----------------
__device__ void slasv2_f32(float F, float G, float H,
                           float& ssmin, float& ssmax,
                           float& snr, float& csr, float& snl, float& csl)
{
    float FT = F, FA = fabsf(F), HT = H, HA = fabsf(H);
    int pmax = 1;
    bool swp = (HA > FA);
    if (swp) { pmax = 3; float t = FT; FT = HT; HT = t; t = FA; FA = HA; HA = t; }
    float GT = G, GA = fabsf(G);
    float clt = 0.f, crt = 0.f, slt = 0.f, srt = 0.f;
    if (GA == 0.0f) {
        ssmin = HA; ssmax = FA;
        clt = 1.0f; crt = 1.0f; slt = 0.0f; srt = 0.0f;
    } else {
        bool gasmal = true;
        if (GA > FA) {
            pmax = 2;
            if (fdivf(FA, GA) < SEPS) {
                gasmal = false;
                ssmax = GA;
                if (HA > 1.0f) ssmin = fdivf(FA, fdivf(GA, HA));
                else           ssmin = __fmul_rn(fdivf(FA, GA), HA);
                clt = 1.0f; slt = fdivf(HT, GT);
                srt = 1.0f; crt = fdivf(FT, GT);
            }
        }
        if (gasmal) {
            float D = __fsub_rn(FA, HA);
            float L = (D == FA) ? 1.0f : fdivf(D, FA);
            float M = fdivf(GT, FT);
            float T = __fsub_rn(2.0f, L);
            float MM = __fmul_rn(M, M);
            float TT = __fmul_rn(T, T);
            float S = fsqrtf_a(__fadd_rn(TT, MM));
            float R = (L == 0.0f) ? fabsf(M) : fsqrtf_a(fmaf(L, L, MM));
            float A = __fmul_rn(0.5f, __fadd_rn(S, R));
            ssmin = fdivf(HA, A);
            ssmax = __fmul_rn(FA, A);
            if (MM == 0.0f) {
                if (L == 0.0f) T = __fmul_rn(copysignf(2.0f, FT), copysignf(1.0f, GT));
                else T = __fadd_rn(fdivf(GT, copysignf(D, FT)), fdivf(M, T));
            } else {
                T = __fmul_rn(__fadd_rn(fdivf(M, __fadd_rn(S, T)),
                                        fdivf(M, __fadd_rn(R, L))),
                              __fadd_rn(1.0f, A));
            }
            float L2 = fsqrtf_a(fmaf(T, T, 4.0f));
            crt = fdivf(2.0f, L2);
            srt = fdivf(T, L2);
            clt = fdivf(fmaf(srt, M, crt), A);
            slt = fdivf(__fmul_rn(fdivf(HT, FT), srt), A);
        }
    }
    if (swp) { csl = srt; snl = crt; csr = slt; snr = clt; }
    else     { csl = clt; snl = slt; csr = crt; snr = srt; }
    float tsign = 1.0f;
    if (pmax == 1) tsign = copysignf(1.0f, csr) * copysignf(1.0f, csl) * copysignf(1.0f, F);
    if (pmax == 2) tsign = copysignf(1.0f, snr) * copysignf(1.0f, csl) * copysignf(1.0f, G);
    if (pmax == 3) tsign = copysignf(1.0f, snr) * copysignf(1.0f, snl) * copysignf(1.0f, H);
    ssmax = copysignf(ssmax, tsign);
    ssmin = copysignf(ssmin, __fmul_rn(tsign, __fmul_rn(copysignf(1.0f, F), copysignf(1.0f, H))));
}

// ---- SGEBD2 Householder (ERROR-CRITICAL, bit-faithful fp32) ----
__device__ __forceinline__ void householder(float a11, float a21,
                                            float& d1, float& v1, float& tau)
{
    if (a21 == 0.0f) {
        tau = 0.0f; v1 = 0.0f; d1 = a11;
    } else {
        float xa = fabsf(a11), ya = fabsf(a21);
        float w_ = fmaxf(xa, ya), z_ = fminf(xa, ya);
        float py;
        if (z_ == 0.0f) py = w_;
        else {
            float r = __fdiv_rn(z_, w_);
            py = __fmul_rn(w_, sqrtf(fmaf(r, r, 1.0f)));
        }
        float beta = -copysignf(py, a11);
        tau = __fdiv_rn(__fsub_rn(beta, a11), beta);
        float rcp = __fdiv_rn(1.0f, __fsub_rn(a11, beta));
        v1 = __fmul_rn(a21, rcp);
        d1 = beta;
    }
}

// One system solve given hoisted Householder state + staged column entries.
__device__ __forceinline__ void solve_sys(float d1, float v1, float tau, float ntau,
                                          float d1sq, float c1, float c2,
                                          float b1v, float b2v,
                                          float a12, float a22,
                                          float& w0, float& w1)
{
    // slarf on column 2 (bit-identical to LAPACK realization)
    const float wv   = fmaf(v1, a22, a12);
    const float temp = __fmul_rn(ntau, wv);
    const float e    = __fadd_rn(a12, temp);
    const float d2   = fmaf(v1, temp, a22);

    const float det  = __fmul_rn(d1, d2);
    const float fro2 = fmaf(d2, d2, fmaf(e, e, d1sq));

    if (fabsf(det) > 2.0f * RCOND * fro2) {
        // FAST: both sigmas provably kept -> pinv(B)=B^-1 triangular solve
        w1 = fdivf(c2, d2);
        w0 = fdivf(fmaf(-e, w1, c1), d1);
    } else {
        // SLOW (rare): verbatim LAPACK slasv2 + jax pinv path
        float ssmin, ssmax, snr, csr, snl, csl;
        slasv2_f32(d1, e, d2, ssmin, ssmax, snr, csr, snl, csl);
        float sigmx = ssmax, sigmn = ssmin;
        float vt00 = csr, vt01 = snr, vt10 = -snr, vt11 = csr;
        float u00 = csl, u01 = -snl, u10 = snl, u11 = csl;
        if (sigmx < 0.0f) { sigmx = -sigmx; vt00 = -vt00; vt01 = -vt01; }
        if (sigmn < 0.0f) { sigmn = -sigmn; vt10 = -vt10; vt11 = -vt11; }
        if (tau != 0.0f) {
            float w0_ = fmaf(v1, u10, u00), t0 = __fmul_rn(ntau, w0_);
            u00 = __fadd_rn(u00, t0); u10 = fmaf(v1, t0, u10);
            float w1_ = fmaf(v1, u11, u01), t1 = __fmul_rn(ntau, w1_);
            u01 = __fadd_rn(u01, t1); u11 = fmaf(v1, t1, u11);
        }
        const float cutoff = __fmul_rn(RCOND, sigmx);
        const bool k1 = (sigmx > cutoff);
        const bool k2 = (sigmn > cutoff);
        const float N00 = k1 ? fdivf(u00, sigmx) : 0.0f;
        const float N01 = k1 ? fdivf(u10, sigmx) : 0.0f;
        const float N10 = k2 ? fdivf(u01, sigmn) : 0.0f;
        const float N11 = k2 ? fdivf(u11, sigmn) : 0.0f;
        const float P00 = fmaf(vt10, N10, __fmul_rn(vt00, N00));
        const float P01 = fmaf(vt10, N11, __fmul_rn(vt00, N01));
        const float P10 = fmaf(vt11, N10, __fmul_rn(vt01, N00));
        const float P11 = fmaf(vt11, N11, __fmul_rn(vt01, N01));
        w0 = fmaf(P01, b2v, __fmul_rn(P00, b1v));
        w1 = fmaf(P11, b2v, __fmul_rn(P10, b1v));
    }
}

// grid = NCHUNK q-chunks x 16 s-pair-chunks = 720 blocks; each thread owns
// two adjacent systems (s0 = 2*pair, s0+1) -> 2x ILP, float4 stores.
__global__ __launch_bounds__(256)
void robust_list_kernel(const int* __restrict__ labels,
                        const float* __restrict__ features,
                        float* __restrict__ out, int write_indices)
{
    __shared__ float scol[MAXTRIP + 1][NSAMP];   // col 0 = p, cols 1.. = q0..
    __shared__ float ssb[NSAMP];                 // y - 0.5

    const int t  = threadIdx.x;
    const int c  = blockIdx.x >> 4;
    const int p  = c_p[c];
    const int q0 = c_q0[c];
    const int ntr = c_n[c];

    // stage only the needed columns (exact ops: sign flip by +-1)
    const int ncols = ntr + 1;
    for (int idx = t; idx < ncols * NSAMP; idx += 256) {
        int cl = idx >> 7, r = idx & 127;
        int cg = (cl == 0) ? p : (q0 + cl - 1);
        float y = 2.0f * (float)labels[r] - 1.0f;
        scol[cl][r] = y * features[r * NDIM + cg];
    }
    if (t < NSAMP) ssb[t] = (2.0f * (float)labels[t] - 1.0f) - 0.5f;
    __syncthreads();

    const int pair = (blockIdx.x & 15) * 256 + t;
    if (pair >= NPAIR2) return;
    const int s0 = pair * 2;

    // decode s0 -> (i, j); s0+1 -> (i2, j2) via increment + row wrap
    int i = (int)floorf((255.0f - fsqrtf_a((float)(65025 - 8 * s0))) * 0.5f);
    if (i > 0 && row_start(i, NSAMP) > s0) i--;
    if (row_start(i + 1, NSAMP) <= s0) i++;
    const int j = s0 - row_start(i, NSAMP) + i + 1;
    int i2 = i, j2 = j + 1;
    if (j2 >= NSAMP) { i2 = i + 1; j2 = i2 + 1; }

    // system A (s0)
    const float b1a = ssb[i],  b2a = ssb[j];
    // system B (s0+1)
    const float b1b = ssb[i2], b2b = ssb[j2];

    float d1a, v1a, taua, d1b, v1b, taub;
    householder(scol[0][i],  scol[0][j],  d1a, v1a, taua);
    householder(scol[0][i2], scol[0][j2], d1b, v1b, taub);
    const float ntaua = -taua, ntaub = -taub;
    const float d1sqa = __fmul_rn(d1a, d1a);
    const float d1sqb = __fmul_rn(d1b, d1b);

    // c = H1 * b (q-invariant)
    const float wva = fmaf(v1a, b2a, b1a), tba = __fmul_rn(ntaua, wva);
    const float c1a = __fadd_rn(b1a, tba), c2a = fmaf(v1a, tba, b2a);
    const float wvb = fmaf(v1b, b2b, b1b), tbb = __fmul_rn(ntaub, wvb);
    const float c1b = __fadd_rn(b1b, tbb), c2b = fmaf(v1b, tbb, b2b);

    float4* o4 = (float4*)out;
    // idx in float2 units is even (s0 even, f*SPAIRS even) -> float4 index = /2
    size_t idx4 = ((size_t)(row_start(p, NDIM) + (q0 - p - 1)) * SPAIRS + (size_t)s0) >> 1;
    float qf = (float)q0;
    const float pf = (float)p;

    #pragma unroll 1
    for (int k = 1; k <= ntr; k++, idx4 += SPAIRS / 2, qf += 1.0f) {
        const float a12a = scol[k][i],  a22a = scol[k][j];
        const float a12b = scol[k][i2], a22b = scol[k][j2];

        float w0a, w1a, w0b, w1b;
        solve_sys(d1a, v1a, taua, ntaua, d1sqa, c1a, c2a, b1a, b2a, a12a, a22a, w0a, w1a);
        solve_sys(d1b, v1b, taub, ntaub, d1sqb, c1b, c2b, b1b, b2b, a12b, a22b, w0b, w1b);

        o4[idx4] = make_float4(w0a, w1a, w0b, w1b);
        if (write_indices) {
            o4[(size_t)(FS / 2) + idx4] = make_float4(pf, qf, pf, qf);
        }
    }
}

extern "C" void kernel_launch(void* const* d_in, const int* in_sizes, int n_in,
                              void* d_out, int out_size)
{
    const int*   labels   = (const int*)d_in[0];     // int32 [128]
    const float* features = (const float*)d_in[1];   // float32 [128,24]
    float* out = (float*)d_out;

    const int write_indices = (out_size >= 2 * FS * 2) ? 1 : 0;

    robust_list_kernel<<<NCHUNK * 16, 256>>>(labels, features, out, write_indices);
}